// round 1
// baseline (speedup 1.0000x reference)
#include <cuda_runtime.h>

// ---------------- problem constants ----------------
#define BATCH 2
#define CH    3
#define IMGH  384
#define IMGW  384
#define IMGPIX (IMGH*IMGW)
#define IMGSZ  (BATCH*CH*IMGPIX)

// ---------------- scratch (device globals; no allocations allowed) ----------
__device__ float g_x3[IMGSZ];
__device__ float g_x6[IMGSZ];
__device__ float g_x9[IMGSZ];
__device__ float g_xg[BATCH];
__device__ float g_G3[6*3*3];
__device__ float g_gb3[6*3];
__device__ float g_G6[4*12*12];
__device__ float g_gb6[4*12];
__device__ float g_G9[2*27*27];
__device__ float g_gb9[2*27];

__device__ __forceinline__ float neg_inf() { return __int_as_float(0xff800000); }

__device__ __forceinline__ void atomicMaxFloat(float* addr, float val) {
    if (val >= 0.f) atomicMax((int*)addr, __float_as_int(val));
    else            atomicMin((unsigned int*)addr, __float_as_uint(val));
}

// ---------------- precompute: G = (Wk^T Wq)/sqrt(D), gb = (Wk^T bq)/sqrt(D) --
__device__ void computeG(const float* __restrict__ Wq, const float* __restrict__ Wk,
                         const float* __restrict__ bq,
                         float* __restrict__ G, float* __restrict__ gb,
                         int heads, int D, int tid, int nthr)
{
    float scale = rsqrtf((float)D);
    int total = heads * D * D;
    for (int i = tid; i < total; i += nthr) {
        int h  = i / (D * D);
        int r  = i % (D * D);
        int d  = r / D;
        int dp = r % D;
        const float* wk = Wk + h * D * D;
        const float* wq = Wq + h * D * D;
        float s = 0.f;
        for (int e = 0; e < D; e++) s += wk[e * D + d] * wq[e * D + dp];
        G[i] = s * scale;
    }
    int totb = heads * D;
    for (int i = tid; i < totb; i += nthr) {
        int h = i / D;
        int d = i % D;
        const float* wk = Wk + h * D * D;
        const float* b  = bq + h * D;
        float s = 0.f;
        for (int e = 0; e < D; e++) s += b[e] * wk[e * D + d];
        gb[i] = s * scale;
    }
}

__global__ void precompute_kernel(const float* __restrict__ w3q, const float* __restrict__ b3q, const float* __restrict__ w3k,
                                  const float* __restrict__ w6q, const float* __restrict__ b6q, const float* __restrict__ w6k,
                                  const float* __restrict__ w9q, const float* __restrict__ b9q, const float* __restrict__ w9k)
{
    int tid = threadIdx.x, n = blockDim.x;
    if (tid < BATCH) g_xg[tid] = neg_inf();
    computeG(w3q, w3k, b3q, g_G3, g_gb3, 6, 3,  tid, n);
    computeG(w6q, w6k, b6q, g_G6, g_gb6, 4, 12, tid, n);
    computeG(w9q, w9k, b9q, g_G9, g_gb9, 2, 27, tid, n);
}

// ---------------- windowed attention stage ---------------------------------
// One thread = one window. Tokens come from a reflect-padded shared tile.
// score_t = (G tok4 + gb) . tok_t ;  out = sum_h hw[h]*(Wv . (sum_t a_t tok_t) + bv)
template<int P, int D, int HEADS, int TW, int TH, bool DOMAX>
__global__ void __launch_bounds__(TW*TH)
attn_kernel(const float* __restrict__ in, float* __restrict__ out,
            const float* __restrict__ Gg, const float* __restrict__ gbg,
            const float* __restrict__ Wvg, const float* __restrict__ bvg,
            const float* __restrict__ hwg)
{
    constexpr int PP    = P * P;
    constexpr int TILEH = (TH + 2) * P;
    constexpr int TILEW = (TW + 2) * P;

    __shared__ float s_tile[CH][TILEH][TILEW];
    __shared__ float s_G [HEADS * D * D];
    __shared__ float s_Wv[HEADS * D * D];
    __shared__ float s_gb[HEADS * D];
    __shared__ float s_bv[HEADS * D];
    __shared__ float s_hw[HEADS];

    const int tid  = threadIdx.x;
    const int nthr = TW * TH;
    const int b    = blockIdx.z;
    const int wi0  = blockIdx.y * TH;
    const int wj0  = blockIdx.x * TW;

    for (int i = tid; i < HEADS * D * D; i += nthr) { s_G[i] = Gg[i]; s_Wv[i] = Wvg[i]; }
    for (int i = tid; i < HEADS * D;     i += nthr) { s_gb[i] = gbg[i]; s_bv[i] = bvg[i]; }
    if (tid < HEADS) s_hw[tid] = hwg[tid];

    // ---- load halo tile with reflect padding ----
    const float* inb = in + (size_t)b * CH * IMGPIX;
    float lmax = neg_inf();
    for (int i = tid; i < CH * TILEH * TILEW; i += nthr) {
        int c   = i / (TILEH * TILEW);
        int rem = i % (TILEH * TILEW);
        int tr  = rem / TILEW;
        int tc  = rem % TILEW;
        int r  = (wi0 - 1) * P + tr;  if (r  < 0) r  = -r;  else if (r  >= IMGH) r  = 2 * IMGH - 2 - r;
        int cc = (wj0 - 1) * P + tc;  if (cc < 0) cc = -cc; else if (cc >= IMGW) cc = 2 * IMGW - 2 - cc;
        float v = inb[c * IMGPIX + r * IMGW + cc];
        s_tile[c][tr][tc] = v;
        if (DOMAX) lmax = fmaxf(lmax, v);
    }
    if (DOMAX) {
        #pragma unroll
        for (int o = 16; o; o >>= 1) lmax = fmaxf(lmax, __shfl_xor_sync(0xffffffff, lmax, o));
        if ((tid & 31) == 0) atomicMaxFloat(&g_xg[b], lmax);
    }
    __syncthreads();

    const int lwj = tid % TW;
    const int lwi = tid / TW;

    float tok4[D];
    #pragma unroll
    for (int c = 0; c < CH; c++)
        #pragma unroll
        for (int pi = 0; pi < P; pi++)
            #pragma unroll
            for (int pj = 0; pj < P; pj++)
                tok4[c * PP + pi * P + pj] = s_tile[c][(lwi + 1) * P + pi][(lwj + 1) * P + pj];

    float mixed[D];
    #pragma unroll
    for (int e = 0; e < D; e++) mixed[e] = 0.f;

    for (int h = 0; h < HEADS; h++) {
        const float* Gh  = &s_G [h * D * D];
        const float* Wvh = &s_Wv[h * D * D];

        float u[D];
        #pragma unroll
        for (int d = 0; d < D; d++) {
            float s = s_gb[h * D + d];
            #pragma unroll
            for (int dp = 0; dp < D; dp++) s += Gh[d * D + dp] * tok4[dp];
            u[d] = s;
        }

        float sc[9];
        float smax = neg_inf();
        #pragma unroll
        for (int di = 0; di < 3; di++)
            #pragma unroll
            for (int dj = 0; dj < 3; dj++) {
                float s = 0.f;
                #pragma unroll
                for (int c = 0; c < CH; c++)
                    #pragma unroll
                    for (int pi = 0; pi < P; pi++)
                        #pragma unroll
                        for (int pj = 0; pj < P; pj++)
                            s += u[c * PP + pi * P + pj] *
                                 s_tile[c][(lwi + di) * P + pi][(lwj + dj) * P + pj];
                sc[di * 3 + dj] = s;
                smax = fmaxf(smax, s);
            }

        float den = 0.f;
        #pragma unroll
        for (int t = 0; t < 9; t++) { float e = __expf(sc[t] - smax); sc[t] = e; den += e; }
        float inv = 1.f / den;

        float wtok[D];
        #pragma unroll
        for (int d = 0; d < D; d++) wtok[d] = 0.f;
        #pragma unroll
        for (int di = 0; di < 3; di++)
            #pragma unroll
            for (int dj = 0; dj < 3; dj++) {
                float a = sc[di * 3 + dj] * inv;
                #pragma unroll
                for (int c = 0; c < CH; c++)
                    #pragma unroll
                    for (int pi = 0; pi < P; pi++)
                        #pragma unroll
                        for (int pj = 0; pj < P; pj++)
                            wtok[c * PP + pi * P + pj] +=
                                a * s_tile[c][(lwi + di) * P + pi][(lwj + dj) * P + pj];
            }

        float hww = s_hw[h];
        #pragma unroll
        for (int e = 0; e < D; e++) {
            float s = s_bv[h * D + e];
            #pragma unroll
            for (int d = 0; d < D; d++) s += Wvh[e * D + d] * wtok[d];
            mixed[e] += hww * s;
        }
    }

    // ---- scatter window back to image ----
    float* outb = out + (size_t)b * CH * IMGPIX;
    const int wi = wi0 + lwi, wj = wj0 + lwj;
    #pragma unroll
    for (int c = 0; c < CH; c++)
        #pragma unroll
        for (int pi = 0; pi < P; pi++)
            #pragma unroll
            for (int pj = 0; pj < P; pj++)
                outb[c * IMGPIX + (wi * P + pi) * IMGW + (wj * P + pj)] =
                    mixed[c * PP + pi * P + pj];
}

// ---------------- fused conv0 (5x5, pad 2, cat[x9,x6,x3]) + dehaze epilogue --
#define CB_X 32
#define CB_Y 8

__global__ void __launch_bounds__(CB_X*CB_Y)
final_kernel(const float* __restrict__ x,
             const float* __restrict__ conv_w, const float* __restrict__ conv_b,
             float* __restrict__ out)
{
    constexpr int TEH = CB_Y + 4, TEW = CB_X + 4;
    __shared__ float s_t[9][TEH][TEW];
    __shared__ float s_w[3 * 9 * 25];
    __shared__ float s_b[3];

    const int tid  = threadIdx.y * CB_X + threadIdx.x;
    const int nthr = CB_X * CB_Y;
    for (int i = tid; i < 675; i += nthr) s_w[i] = conv_w[i];
    if (tid < 3) s_b[tid] = conv_b[tid];

    const int b  = blockIdx.z;
    const int y0 = blockIdx.y * CB_Y;
    const int x0 = blockIdx.x * CB_X;

    for (int i = tid; i < 9 * TEH * TEW; i += nthr) {
        int ci  = i / (TEH * TEW);
        int rem = i % (TEH * TEW);
        int ty  = rem / TEW;
        int tx  = rem % TEW;
        int gy = y0 + ty - 2, gx = x0 + tx - 2;
        float v = 0.f;
        if (gy >= 0 && gy < IMGH && gx >= 0 && gx < IMGW) {
            const float* src = (ci < 3) ? g_x9 : (ci < 6) ? g_x6 : g_x3;
            v = src[(((size_t)b * CH + (ci % 3)) * IMGH + gy) * IMGW + gx];
        }
        s_t[ci][ty][tx] = v;
    }
    __syncthreads();

    const int ty = threadIdx.y, tx = threadIdx.x;
    float acc0 = s_b[0], acc1 = s_b[1], acc2 = s_b[2];
    #pragma unroll
    for (int ci = 0; ci < 9; ci++)
        #pragma unroll
        for (int kh = 0; kh < 5; kh++)
            #pragma unroll
            for (int kw = 0; kw < 5; kw++) {
                float v = s_t[ci][ty + kh][tx + kw];
                acc0 += s_w[(0 * 9 + ci) * 25 + kh * 5 + kw] * v;
                acc1 += s_w[(1 * 9 + ci) * 25 + kh * 5 + kw] * v;
                acc2 += s_w[(2 * 9 + ci) * 25 + kh * 5 + kw] * v;
            }

    const float xg = g_xg[b];
    const int gy = y0 + ty, gx = x0 + tx;
    float acc[3] = {acc0, acc1, acc2};
    #pragma unroll
    for (int co = 0; co < 3; co++) {
        float x0v = fmaxf(acc[co], 0.f);
        size_t idx = (((size_t)b * CH + co) * IMGH + gy) * IMGW + gx;
        float xv = x[idx];
        out[idx] = fmaxf(xv * x0v + (xg - x0v), 0.f);
    }
}

// ---------------- launch ----------------------------------------------------
extern "C" void kernel_launch(void* const* d_in, const int* in_sizes, int n_in,
                              void* d_out, int out_size)
{
    (void)in_sizes; (void)n_in; (void)out_size;

    const float* x    = (const float*)d_in[0];
    const float* w3q  = (const float*)d_in[1];
    const float* b3q  = (const float*)d_in[2];
    const float* w3k  = (const float*)d_in[3];
    const float* w3v  = (const float*)d_in[5];
    const float* b3v  = (const float*)d_in[6];
    const float* hw3  = (const float*)d_in[7];
    const float* w6q  = (const float*)d_in[8];
    const float* b6q  = (const float*)d_in[9];
    const float* w6k  = (const float*)d_in[10];
    const float* w6v  = (const float*)d_in[12];
    const float* b6v  = (const float*)d_in[13];
    const float* hw6  = (const float*)d_in[14];
    const float* w9q  = (const float*)d_in[15];
    const float* b9q  = (const float*)d_in[16];
    const float* w9k  = (const float*)d_in[17];
    const float* w9v  = (const float*)d_in[19];
    const float* b9v  = (const float*)d_in[20];
    const float* hw9  = (const float*)d_in[21];
    const float* cw   = (const float*)d_in[22];
    const float* cb   = (const float*)d_in[23];

    float *x3, *x6, *x9, *G3, *gb3, *G6, *gb6, *G9, *gb9;
    cudaGetSymbolAddress((void**)&x3,  g_x3);
    cudaGetSymbolAddress((void**)&x6,  g_x6);
    cudaGetSymbolAddress((void**)&x9,  g_x9);
    cudaGetSymbolAddress((void**)&G3,  g_G3);
    cudaGetSymbolAddress((void**)&gb3, g_gb3);
    cudaGetSymbolAddress((void**)&G6,  g_G6);
    cudaGetSymbolAddress((void**)&gb6, g_gb6);
    cudaGetSymbolAddress((void**)&G9,  g_G9);
    cudaGetSymbolAddress((void**)&gb9, g_gb9);

    precompute_kernel<<<1, 256>>>(w3q, b3q, w3k, w6q, b6q, w6k, w9q, b9q, w9k);

    // stage p=1: 384x384 windows, 16x16 per block
    attn_kernel<1, 3, 6, 16, 16, true ><<<dim3(24, 24, BATCH), 256>>>(x,  x3, G3, gb3, w3v, b3v, hw3);
    // stage p=2: 192x192 windows
    attn_kernel<2, 12, 4, 16, 16, false><<<dim3(12, 12, BATCH), 256>>>(x3, x6, G6, gb6, w6v, b6v, hw6);
    // stage p=3: 128x128 windows, 16x8 per block
    attn_kernel<3, 27, 2, 16, 8,  false><<<dim3(8, 16, BATCH), 128>>>(x6, x9, G9, gb9, w9v, b9v, hw9);

    final_kernel<<<dim3(IMGW / CB_X, IMGH / CB_Y, BATCH), dim3(CB_X, CB_Y)>>>(x, cw, cb, (float*)d_out);
}

// round 2
// speedup vs baseline: 1.0240x; 1.0240x over previous
#include <cuda_runtime.h>

// ---------------- problem constants ----------------
#define BATCH 2
#define CH    3
#define IMGH  384
#define IMGW  384
#define IMGPIX (IMGH*IMGW)
#define IMGSZ  (BATCH*CH*IMGPIX)
#define NB1   576   // blocks per batch in the p=1 stage (24*24)

// ---------------- scratch (device globals; no allocations allowed) ----------
__device__ float g_x3[IMGSZ];
__device__ float g_x6[IMGSZ];
__device__ float g_x9[IMGSZ];
__device__ float g_bmax[BATCH*NB1];

__device__ __forceinline__ float neg_inf() { return __int_as_float(0xff800000); }

// ---------------- swizzled shared-tile addressing ---------------------------
// Rows padded to 32 floats (stride == 0 mod 32 banks). Swizzles chosen so the
// warp's (lwi, lwj) lane layout maps to distinct banks.
template<int P,int TILEH>
__device__ __forceinline__ int sm_idx(int c,int r,int col){
    int sw;
    if (P==1)      sw = col ^ ((r & 1) << 4);
    else if (P==3) sw = col ^ ((r & 3) << 3);
    else { // P==2 scalar view of float2 words
        int wc = col >> 1;
        int wcs = (wc + (((r >> 1) & 3) << 2)) & 15;
        sw = wcs * 2 + (col & 1);
    }
    return (c * TILEH + r) * 32 + sw;
}
template<int TILEH>
__device__ __forceinline__ int sm_idx2(int c,int r,int wc){ // P==2 word index
    int wcs = (wc + (((r >> 1) & 3) << 2)) & 15;
    return (c * TILEH + r) * 16 + wcs;
}

// ---------------- windowed attention stage ---------------------------------
// One thread = one window, ALL heads fused (token reads shared across heads).
// score_t = (G^T tok4 + gb) . tok_t ;  out = sum_h [hw_h*Wv_h . (sum_t a_t tok_t) + hw_h*bv_h]
// G (transposed), Wv' (transposed, hw folded) built per-block from global weights.
template<int P,int D,int HEADS,int TW,int TH,bool DOMAX>
__global__ void __launch_bounds__(TW*TH)
attn_kernel(const float* __restrict__ in, float* __restrict__ out,
            const float* __restrict__ Wq, const float* __restrict__ bq,
            const float* __restrict__ Wk,
            const float* __restrict__ Wv, const float* __restrict__ bv,
            const float* __restrict__ hw)
{
    constexpr int PP    = P * P;
    constexpr int DP    = (D + 3) & ~3;       // pad inner dim to float4
    constexpr int NTHR  = TW * TH;
    constexpr int TILEH = (TH + 2) * P;
    constexpr int TILEW = (TW + 2) * P;
    static_assert(TILEW <= 32, "tile row must fit padded 32-float row");

    __shared__ __align__(16) float s_tile[CH * TILEH * 32];
    __shared__ __align__(16) float s_Gt [HEADS * D * DP];   // [h][m][n]
    __shared__ __align__(16) float s_Wvt[HEADS * D * DP];   // [h][d][e], hw folded
    __shared__ __align__(16) float s_gbp[HEADS * DP];
    __shared__ __align__(16) float s_bvp[HEADS * DP];       // hw folded
    __shared__ float s_red[(NTHR/32) > 0 ? (NTHR/32) : 1];

    const int tid = threadIdx.x;
    const int b   = blockIdx.z;
    const int wi0 = blockIdx.y * TH;
    const int wj0 = blockIdx.x * TW;
    const float scale = rsqrtf((float)D);

    // ---- build folded weights (reads L1-cached globals) ----
    for (int i = tid; i < HEADS * D * DP; i += NTHR) {
        int h = i / (D * DP); int r = i % (D * DP); int m = r / DP; int n = r % DP;
        float g = 0.f, wvv = 0.f;
        if (n < D) {
            const float* wk = Wk + h * D * D;
            const float* wq = Wq + h * D * D;
            float s = 0.f;
            #pragma unroll
            for (int e = 0; e < D; e++) s += wk[e * D + n] * wq[e * D + m];
            g   = s * scale;
            wvv = hw[h] * Wv[h * D * D + n * D + m];
        }
        s_Gt[i] = g; s_Wvt[i] = wvv;
    }
    for (int i = tid; i < HEADS * DP; i += NTHR) {
        int h = i / DP, n = i % DP;
        float gb = 0.f, bvv = 0.f;
        if (n < D) {
            const float* wk = Wk + h * D * D;
            float s = 0.f;
            #pragma unroll
            for (int e = 0; e < D; e++) s += bq[h * D + e] * wk[e * D + n];
            gb  = s * scale;
            bvv = hw[h] * bv[h * D + n];
        }
        s_gbp[i] = gb; s_bvp[i] = bvv;
    }

    // ---- load halo tile with reflect padding (swizzled store) ----
    const float* inb = in + (size_t)b * CH * IMGPIX;
    float lmax = neg_inf();
    for (int i = tid; i < CH * TILEH * TILEW; i += NTHR) {
        int c   = i / (TILEH * TILEW);
        int rem = i % (TILEH * TILEW);
        int tr  = rem / TILEW;
        int tc  = rem % TILEW;
        int rr = (wi0 - 1) * P + tr; if (rr < 0) rr = -rr; else if (rr >= IMGH) rr = 2 * IMGH - 2 - rr;
        int cc = (wj0 - 1) * P + tc; if (cc < 0) cc = -cc; else if (cc >= IMGW) cc = 2 * IMGW - 2 - cc;
        float v = inb[c * IMGPIX + rr * IMGW + cc];
        s_tile[sm_idx<P, TILEH>(c, tr, tc)] = v;
        if (DOMAX) lmax = fmaxf(lmax, v);
    }
    if (DOMAX) {
        #pragma unroll
        for (int o = 16; o; o >>= 1) lmax = fmaxf(lmax, __shfl_xor_sync(0xffffffffu, lmax, o));
        if ((tid & 31) == 0) s_red[tid >> 5] = lmax;
    }
    __syncthreads();
    if (DOMAX && tid == 0) {
        float m = s_red[0];
        #pragma unroll
        for (int w = 1; w < NTHR / 32; w++) m = fmaxf(m, s_red[w]);
        g_bmax[b * NB1 + blockIdx.y * gridDim.x + blockIdx.x] = m;
    }

    const int lwj = tid % TW;
    const int lwi = tid / TW;

    // ---- center token ----
    float tok4[D];
    if constexpr (P == 2) {
        #pragma unroll
        for (int c = 0; c < CH; c++)
            #pragma unroll
            for (int pi = 0; pi < 2; pi++) {
                float2 v = ((const float2*)s_tile)[sm_idx2<TILEH>(c, (lwi + 1) * 2 + pi, lwj + 1)];
                tok4[c * 4 + pi * 2] = v.x; tok4[c * 4 + pi * 2 + 1] = v.y;
            }
    } else {
        #pragma unroll
        for (int c = 0; c < CH; c++)
            #pragma unroll
            for (int pi = 0; pi < P; pi++)
                #pragma unroll
                for (int pj = 0; pj < P; pj++)
                    tok4[c * PP + pi * P + pj] =
                        s_tile[sm_idx<P, TILEH>(c, (lwi + 1) * P + pi, (lwj + 1) * P + pj)];
    }

    // ---- u = G^T tok4 + gb (float4-vectorized over output dim) ----
    float u[HEADS][DP];
    #pragma unroll
    for (int h = 0; h < HEADS; h++)
        #pragma unroll
        for (int e4 = 0; e4 < DP; e4 += 4) {
            float4 v = *(const float4*)&s_gbp[h * DP + e4];
            u[h][e4] = v.x; u[h][e4+1] = v.y; u[h][e4+2] = v.z; u[h][e4+3] = v.w;
        }
    #pragma unroll
    for (int h = 0; h < HEADS; h++)
        #pragma unroll
        for (int m = 0; m < D; m++) {
            float t = tok4[m];
            #pragma unroll
            for (int e4 = 0; e4 < DP; e4 += 4) {
                float4 g = *(const float4*)&s_Gt[(h * D + m) * DP + e4];
                u[h][e4]   += g.x * t; u[h][e4+1] += g.y * t;
                u[h][e4+2] += g.z * t; u[h][e4+3] += g.w * t;
            }
        }

    // ---- scores (all heads per token read) ----
    float sc[HEADS][9], smax[HEADS];
    #pragma unroll
    for (int h = 0; h < HEADS; h++) smax[h] = neg_inf();

    #pragma unroll
    for (int di = 0; di < 3; di++)
    #pragma unroll
    for (int dj = 0; dj < 3; dj++) {
        float s[HEADS];
        #pragma unroll
        for (int h = 0; h < HEADS; h++) s[h] = 0.f;
        if constexpr (P == 2) {
            #pragma unroll
            for (int c = 0; c < CH; c++)
                #pragma unroll
                for (int pi = 0; pi < 2; pi++) {
                    float2 v = ((const float2*)s_tile)[sm_idx2<TILEH>(c, (lwi + di) * 2 + pi, lwj + dj)];
                    int e = c * 4 + pi * 2;
                    #pragma unroll
                    for (int h = 0; h < HEADS; h++) s[h] += u[h][e] * v.x + u[h][e+1] * v.y;
                }
        } else {
            #pragma unroll
            for (int c = 0; c < CH; c++)
                #pragma unroll
                for (int pi = 0; pi < P; pi++)
                    #pragma unroll
                    for (int pj = 0; pj < P; pj++) {
                        float v = s_tile[sm_idx<P, TILEH>(c, (lwi + di) * P + pi, (lwj + dj) * P + pj)];
                        int e = c * PP + pi * P + pj;
                        #pragma unroll
                        for (int h = 0; h < HEADS; h++) s[h] += u[h][e] * v;
                    }
        }
        const int t = di * 3 + dj;
        #pragma unroll
        for (int h = 0; h < HEADS; h++) { sc[h][t] = s[h]; smax[h] = fmaxf(smax[h], s[h]); }
    }

    #pragma unroll
    for (int h = 0; h < HEADS; h++) {
        float den = 0.f;
        #pragma unroll
        for (int t = 0; t < 9; t++) { float e = __expf(sc[h][t] - smax[h]); sc[h][t] = e; den += e; }
        float inv = 1.f / den;
        #pragma unroll
        for (int t = 0; t < 9; t++) sc[h][t] *= inv;
    }

    // ---- weighted token sum (all heads per token read) ----
    float acc[HEADS][D];
    #pragma unroll
    for (int h = 0; h < HEADS; h++)
        #pragma unroll
        for (int d = 0; d < D; d++) acc[h][d] = 0.f;

    #pragma unroll
    for (int di = 0; di < 3; di++)
    #pragma unroll
    for (int dj = 0; dj < 3; dj++) {
        const int t = di * 3 + dj;
        if constexpr (P == 2) {
            #pragma unroll
            for (int c = 0; c < CH; c++)
                #pragma unroll
                for (int pi = 0; pi < 2; pi++) {
                    float2 v = ((const float2*)s_tile)[sm_idx2<TILEH>(c, (lwi + di) * 2 + pi, lwj + dj)];
                    int e = c * 4 + pi * 2;
                    #pragma unroll
                    for (int h = 0; h < HEADS; h++) { acc[h][e] += sc[h][t] * v.x; acc[h][e+1] += sc[h][t] * v.y; }
                }
        } else {
            #pragma unroll
            for (int c = 0; c < CH; c++)
                #pragma unroll
                for (int pi = 0; pi < P; pi++)
                    #pragma unroll
                    for (int pj = 0; pj < P; pj++) {
                        float v = s_tile[sm_idx<P, TILEH>(c, (lwi + di) * P + pi, (lwj + dj) * P + pj)];
                        int e = c * PP + pi * P + pj;
                        #pragma unroll
                        for (int h = 0; h < HEADS; h++) acc[h][e] += sc[h][t] * v;
                    }
        }
    }

    // ---- output projection (hw folded into Wv, bv), float4-vectorized ----
    float part[DP];
    #pragma unroll
    for (int e = 0; e < DP; e++) part[e] = 0.f;
    #pragma unroll
    for (int h = 0; h < HEADS; h++) {
        #pragma unroll
        for (int e4 = 0; e4 < DP; e4 += 4) {
            float4 v = *(const float4*)&s_bvp[h * DP + e4];
            part[e4] += v.x; part[e4+1] += v.y; part[e4+2] += v.z; part[e4+3] += v.w;
        }
        #pragma unroll
        for (int m = 0; m < D; m++) {
            float a = acc[h][m];
            #pragma unroll
            for (int e4 = 0; e4 < DP; e4 += 4) {
                float4 w = *(const float4*)&s_Wvt[(h * D + m) * DP + e4];
                part[e4]   += w.x * a; part[e4+1] += w.y * a;
                part[e4+2] += w.z * a; part[e4+3] += w.w * a;
            }
        }
    }

    // ---- scatter window back to image ----
    float* outb = out + (size_t)b * CH * IMGPIX;
    const int wi = wi0 + lwi, wj = wj0 + lwj;
    if constexpr (P == 2) {
        #pragma unroll
        for (int c = 0; c < CH; c++)
            #pragma unroll
            for (int pi = 0; pi < 2; pi++)
                *(float2*)&outb[c * IMGPIX + (wi * 2 + pi) * IMGW + wj * 2] =
                    make_float2(part[c * 4 + pi * 2], part[c * 4 + pi * 2 + 1]);
    } else {
        #pragma unroll
        for (int c = 0; c < CH; c++)
            #pragma unroll
            for (int pi = 0; pi < P; pi++)
                #pragma unroll
                for (int pj = 0; pj < P; pj++)
                    outb[c * IMGPIX + (wi * P + pi) * IMGW + (wj * P + pj)] =
                        part[c * PP + pi * P + pj];
    }
}

// ---------------- fused conv0 (5x5, pad 2, cat[x9,x6,x3]) + dehaze epilogue --
#define CB_X 32
#define CB_Y 8

__global__ void __launch_bounds__(CB_X*CB_Y)
final_kernel(const float* __restrict__ x,
             const float* __restrict__ conv_w, const float* __restrict__ conv_b,
             float* __restrict__ out)
{
    constexpr int TEH = CB_Y + 4, TEW = CB_X + 4;
    constexpr int NTHR = CB_X * CB_Y;
    __shared__ float s_t[9][TEH][TEW];
    __shared__ float s_w[3 * 9 * 25];
    __shared__ float s_b[3];
    __shared__ float s_red[NTHR / 32];

    const int tid = threadIdx.y * CB_X + threadIdx.x;
    for (int i = tid; i < 675; i += NTHR) s_w[i] = conv_w[i];
    if (tid < 3) s_b[tid] = conv_b[tid];

    const int b  = blockIdx.z;
    const int y0 = blockIdx.y * CB_Y;
    const int x0 = blockIdx.x * CB_X;

    // xg = max over x (reduced from per-block maxes of the p=1 stage)
    float m = neg_inf();
    for (int i = tid; i < NB1; i += NTHR) m = fmaxf(m, g_bmax[b * NB1 + i]);
    #pragma unroll
    for (int o = 16; o; o >>= 1) m = fmaxf(m, __shfl_xor_sync(0xffffffffu, m, o));
    if ((tid & 31) == 0) s_red[tid >> 5] = m;

    for (int i = tid; i < 9 * TEH * TEW; i += NTHR) {
        int ci  = i / (TEH * TEW);
        int rem = i % (TEH * TEW);
        int ty  = rem / TEW;
        int tx  = rem % TEW;
        int gy = y0 + ty - 2, gx = x0 + tx - 2;
        float v = 0.f;
        if (gy >= 0 && gy < IMGH && gx >= 0 && gx < IMGW) {
            const float* src = (ci < 3) ? g_x9 : (ci < 6) ? g_x6 : g_x3;
            v = src[(((size_t)b * CH + (ci % 3)) * IMGH + gy) * IMGW + gx];
        }
        s_t[ci][ty][tx] = v;
    }
    __syncthreads();

    float xg = s_red[0];
    #pragma unroll
    for (int w = 1; w < NTHR / 32; w++) xg = fmaxf(xg, s_red[w]);

    const int ty = threadIdx.y, tx = threadIdx.x;
    float acc0 = s_b[0], acc1 = s_b[1], acc2 = s_b[2];
    #pragma unroll
    for (int ci = 0; ci < 9; ci++)
        #pragma unroll
        for (int kh = 0; kh < 5; kh++)
            #pragma unroll
            for (int kw = 0; kw < 5; kw++) {
                float v = s_t[ci][ty + kh][tx + kw];
                acc0 += s_w[(0 * 9 + ci) * 25 + kh * 5 + kw] * v;
                acc1 += s_w[(1 * 9 + ci) * 25 + kh * 5 + kw] * v;
                acc2 += s_w[(2 * 9 + ci) * 25 + kh * 5 + kw] * v;
            }

    const int gy = y0 + ty, gx = x0 + tx;
    float acc[3] = {acc0, acc1, acc2};
    #pragma unroll
    for (int co = 0; co < 3; co++) {
        float x0v = fmaxf(acc[co], 0.f);
        size_t idx = (((size_t)b * CH + co) * IMGH + gy) * IMGW + gx;
        float xv = x[idx];
        out[idx] = fmaxf(xv * x0v + (xg - x0v), 0.f);
    }
}

// ---------------- launch ----------------------------------------------------
extern "C" void kernel_launch(void* const* d_in, const int* in_sizes, int n_in,
                              void* d_out, int out_size)
{
    (void)in_sizes; (void)n_in; (void)out_size;

    const float* x    = (const float*)d_in[0];
    const float* w3q  = (const float*)d_in[1];
    const float* b3q  = (const float*)d_in[2];
    const float* w3k  = (const float*)d_in[3];
    const float* w3v  = (const float*)d_in[5];
    const float* b3v  = (const float*)d_in[6];
    const float* hw3  = (const float*)d_in[7];
    const float* w6q  = (const float*)d_in[8];
    const float* b6q  = (const float*)d_in[9];
    const float* w6k  = (const float*)d_in[10];
    const float* w6v  = (const float*)d_in[12];
    const float* b6v  = (const float*)d_in[13];
    const float* hw6  = (const float*)d_in[14];
    const float* w9q  = (const float*)d_in[15];
    const float* b9q  = (const float*)d_in[16];
    const float* w9k  = (const float*)d_in[17];
    const float* w9v  = (const float*)d_in[19];
    const float* b9v  = (const float*)d_in[20];
    const float* hw9  = (const float*)d_in[21];
    const float* cw   = (const float*)d_in[22];
    const float* cb   = (const float*)d_in[23];

    float *x3, *x6, *x9;
    cudaGetSymbolAddress((void**)&x3, g_x3);
    cudaGetSymbolAddress((void**)&x6, g_x6);
    cudaGetSymbolAddress((void**)&x9, g_x9);

    // stage p=1: 384x384 windows, 16x16 per block, 6 heads D=3 (+ image max)
    attn_kernel<1, 3, 6, 16, 16, true ><<<dim3(24, 24, BATCH), 256>>>(x,  x3, w3q, b3q, w3k, w3v, b3v, hw3);
    // stage p=2: 192x192 windows, 8x8 per block, 4 heads D=12
    attn_kernel<2, 12, 4, 8, 8, false><<<dim3(24, 24, BATCH), 64>>>(x3, x6, w6q, b6q, w6k, w6v, b6v, hw6);
    // stage p=3: 128x128 windows, 8x8 per block, 2 heads D=27
    attn_kernel<3, 27, 2, 8, 8, false><<<dim3(16, 16, BATCH), 64>>>(x6, x9, w9q, b9q, w9k, w9v, b9v, hw9);

    final_kernel<<<dim3(IMGW / CB_X, IMGH / CB_Y, BATCH), dim3(CB_X, CB_Y)>>>(x, cw, cb, (float*)d_out);
}

// round 3
// speedup vs baseline: 1.0816x; 1.0562x over previous
#include <cuda_runtime.h>

// ---------------- problem constants ----------------
#define BATCH 2
#define CH    3
#define IMGH  384
#define IMGW  384
#define IMGPIX (IMGH*IMGW)
#define IMGSZ  (BATCH*CH*IMGPIX)
#define NB1   576   // blocks per batch in the p=1 stage (24*24)

// ---------------- scratch (device globals; no allocations allowed) ----------
__device__ float g_x3[IMGSZ];
__device__ float g_x6[IMGSZ];
__device__ float g_x9[IMGSZ];
__device__ float g_bmax[BATCH*NB1];

__device__ __forceinline__ float neg_inf() { return __int_as_float(0xff800000); }

// ---------------- swizzled shared-tile addressing ---------------------------
template<int P,int TILEH>
__device__ __forceinline__ int sm_idx(int c,int r,int col){
    int sw;
    if (P==1)      sw = col ^ ((r & 1) << 4);
    else if (P==3) sw = col ^ ((r & 3) << 3);
    else {
        int wc = col >> 1;
        int wcs = (wc + (((r >> 1) & 3) << 2)) & 15;
        sw = wcs * 2 + (col & 1);
    }
    return (c * TILEH + r) * 32 + sw;
}
template<int TILEH>
__device__ __forceinline__ int sm_idx2(int c,int r,int wc){ // P==2 float2-word index
    int wcs = (wc + (((r >> 1) & 3) << 2)) & 15;
    return (c * TILEH + r) * 16 + wcs;
}

// ============================================================================
// p=1 stage: one thread per window, all 6 heads fused (D=3, tiny registers).
// Also computes per-block image max for xg.
// ============================================================================
template<int TW,int TH>
__global__ void __launch_bounds__(TW*TH)
attn1_kernel(const float* __restrict__ in, float* __restrict__ out,
             const float* __restrict__ Wq, const float* __restrict__ bq,
             const float* __restrict__ Wk,
             const float* __restrict__ Wv, const float* __restrict__ bv,
             const float* __restrict__ hw)
{
    constexpr int P = 1, D = 3, HEADS = 6, DP = 4;
    constexpr int NTHR  = TW * TH;
    constexpr int TILEH = TH + 2;
    constexpr int TILEW = TW + 2;

    __shared__ __align__(16) float s_tile[CH * TILEH * 32];
    __shared__ __align__(16) float s_Gt [HEADS * D * DP];
    __shared__ __align__(16) float s_Wvt[HEADS * D * DP];
    __shared__ __align__(16) float s_gbp[HEADS * DP];
    __shared__ __align__(16) float s_bvp[HEADS * DP];
    __shared__ float s_red[NTHR / 32];

    const int tid = threadIdx.x;
    const int b   = blockIdx.z;
    const int wi0 = blockIdx.y * TH;
    const int wj0 = blockIdx.x * TW;
    const float scale = rsqrtf((float)D);

    for (int i = tid; i < HEADS * D * DP; i += NTHR) {
        int h = i / (D * DP); int r = i % (D * DP); int m = r / DP; int n = r % DP;
        float g = 0.f, wvv = 0.f;
        if (n < D) {
            const float* wk = Wk + h * D * D;
            const float* wq = Wq + h * D * D;
            float s = 0.f;
            #pragma unroll
            for (int e = 0; e < D; e++) s += wk[e * D + n] * wq[e * D + m];
            g   = s * scale;
            wvv = hw[h] * Wv[h * D * D + n * D + m];
        }
        s_Gt[i] = g; s_Wvt[i] = wvv;
    }
    for (int i = tid; i < HEADS * DP; i += NTHR) {
        int h = i / DP, n = i % DP;
        float gb = 0.f, bvv = 0.f;
        if (n < D) {
            const float* wk = Wk + h * D * D;
            float s = 0.f;
            #pragma unroll
            for (int e = 0; e < D; e++) s += bq[h * D + e] * wk[e * D + n];
            gb  = s * scale;
            bvv = hw[h] * bv[h * D + n];
        }
        s_gbp[i] = gb; s_bvp[i] = bvv;
    }

    const float* inb = in + (size_t)b * CH * IMGPIX;
    float lmax = neg_inf();
    for (int i = tid; i < CH * TILEH * TILEW; i += NTHR) {
        int c   = i / (TILEH * TILEW);
        int rem = i % (TILEH * TILEW);
        int tr  = rem / TILEW;
        int tc  = rem % TILEW;
        int rr = wi0 - 1 + tr; if (rr < 0) rr = -rr; else if (rr >= IMGH) rr = 2 * IMGH - 2 - rr;
        int cc = wj0 - 1 + tc; if (cc < 0) cc = -cc; else if (cc >= IMGW) cc = 2 * IMGW - 2 - cc;
        float v = inb[c * IMGPIX + rr * IMGW + cc];
        s_tile[sm_idx<P, TILEH>(c, tr, tc)] = v;
        lmax = fmaxf(lmax, v);
    }
    #pragma unroll
    for (int o = 16; o; o >>= 1) lmax = fmaxf(lmax, __shfl_xor_sync(0xffffffffu, lmax, o));
    if ((tid & 31) == 0) s_red[tid >> 5] = lmax;
    __syncthreads();
    if (tid == 0) {
        float m = s_red[0];
        #pragma unroll
        for (int w = 1; w < NTHR / 32; w++) m = fmaxf(m, s_red[w]);
        g_bmax[b * NB1 + blockIdx.y * gridDim.x + blockIdx.x] = m;
    }

    const int lwj = tid % TW;
    const int lwi = tid / TW;

    float tok4[D];
    #pragma unroll
    for (int c = 0; c < CH; c++)
        tok4[c] = s_tile[sm_idx<P, TILEH>(c, lwi + 1, lwj + 1)];

    float u[HEADS][DP];
    #pragma unroll
    for (int h = 0; h < HEADS; h++) {
        float4 v = *(const float4*)&s_gbp[h * DP];
        u[h][0] = v.x; u[h][1] = v.y; u[h][2] = v.z; u[h][3] = v.w;
    }
    #pragma unroll
    for (int h = 0; h < HEADS; h++)
        #pragma unroll
        for (int m = 0; m < D; m++) {
            float4 g = *(const float4*)&s_Gt[(h * D + m) * DP];
            float t = tok4[m];
            u[h][0] += g.x * t; u[h][1] += g.y * t; u[h][2] += g.z * t; u[h][3] += g.w * t;
        }

    float sc[HEADS][9], smax[HEADS];
    #pragma unroll
    for (int h = 0; h < HEADS; h++) smax[h] = neg_inf();

    #pragma unroll
    for (int di = 0; di < 3; di++)
    #pragma unroll
    for (int dj = 0; dj < 3; dj++) {
        float s[HEADS];
        #pragma unroll
        for (int h = 0; h < HEADS; h++) s[h] = 0.f;
        #pragma unroll
        for (int c = 0; c < CH; c++) {
            float v = s_tile[sm_idx<P, TILEH>(c, lwi + di, lwj + dj)];
            #pragma unroll
            for (int h = 0; h < HEADS; h++) s[h] += u[h][c] * v;
        }
        const int t = di * 3 + dj;
        #pragma unroll
        for (int h = 0; h < HEADS; h++) { sc[h][t] = s[h]; smax[h] = fmaxf(smax[h], s[h]); }
    }

    #pragma unroll
    for (int h = 0; h < HEADS; h++) {
        float den = 0.f;
        #pragma unroll
        for (int t = 0; t < 9; t++) { float e = __expf(sc[h][t] - smax[h]); sc[h][t] = e; den += e; }
        float inv = 1.f / den;
        #pragma unroll
        for (int t = 0; t < 9; t++) sc[h][t] *= inv;
    }

    float acc[HEADS][D];
    #pragma unroll
    for (int h = 0; h < HEADS; h++)
        #pragma unroll
        for (int d = 0; d < D; d++) acc[h][d] = 0.f;

    #pragma unroll
    for (int di = 0; di < 3; di++)
    #pragma unroll
    for (int dj = 0; dj < 3; dj++) {
        const int t = di * 3 + dj;
        #pragma unroll
        for (int c = 0; c < CH; c++) {
            float v = s_tile[sm_idx<P, TILEH>(c, lwi + di, lwj + dj)];
            #pragma unroll
            for (int h = 0; h < HEADS; h++) acc[h][c] += sc[h][t] * v;
        }
    }

    float part[DP];
    #pragma unroll
    for (int e = 0; e < DP; e++) part[e] = 0.f;
    #pragma unroll
    for (int h = 0; h < HEADS; h++) {
        float4 bvv = *(const float4*)&s_bvp[h * DP];
        part[0] += bvv.x; part[1] += bvv.y; part[2] += bvv.z; part[3] += bvv.w;
        #pragma unroll
        for (int m = 0; m < D; m++) {
            float4 w = *(const float4*)&s_Wvt[(h * D + m) * DP];
            float a = acc[h][m];
            part[0] += w.x * a; part[1] += w.y * a; part[2] += w.z * a; part[3] += w.w * a;
        }
    }

    float* outb = out + (size_t)b * CH * IMGPIX;
    const int wi = wi0 + lwi, wj = wj0 + lwj;
    #pragma unroll
    for (int c = 0; c < CH; c++)
        outb[c * IMGPIX + wi * IMGW + wj] = part[c];
}

// ============================================================================
// p=2 / p=3 stages: one warp-group per head (h = tid / NW). Token LDS keeps the
// conflict-free round-2 lane layout; weight reads are warp-uniform broadcasts.
// Head partials combined via odd-stride shared scratch.
// ============================================================================
template<int P,int D,int HEADS,int TW,int TH>
__global__ void __launch_bounds__(TW*TH*HEADS)
attn_split(const float* __restrict__ in, float* __restrict__ out,
           const float* __restrict__ Wq, const float* __restrict__ bq,
           const float* __restrict__ Wk,
           const float* __restrict__ Wv, const float* __restrict__ bv,
           const float* __restrict__ hw)
{
    constexpr int PP    = P * P;
    constexpr int DP    = (D + 3) & ~3;
    constexpr int DR    = D | 1;            // odd stride for conflict-free scratch
    constexpr int NW    = TW * TH;
    constexpr int NTHR  = NW * HEADS;
    constexpr int TILEH = (TH + 2) * P;
    constexpr int TILEW = (TW + 2) * P;
    static_assert(TILEW <= 32, "tile row must fit padded 32-float row");

    __shared__ __align__(16) float s_tile[CH * TILEH * 32];
    __shared__ __align__(16) float s_Gt [HEADS * D * DP];
    __shared__ __align__(16) float s_Wvt[HEADS * D * DP];
    __shared__ __align__(16) float s_gbp[HEADS * DP];
    __shared__ __align__(16) float s_bvp[HEADS * DP];
    __shared__ float s_part[(HEADS - 1) * NW * DR];

    const int tid = threadIdx.x;
    const int b   = blockIdx.z;
    const int wi0 = blockIdx.y * TH;
    const int wj0 = blockIdx.x * TW;
    const float scale = rsqrtf((float)D);

    for (int i = tid; i < HEADS * D * DP; i += NTHR) {
        int h = i / (D * DP); int r = i % (D * DP); int m = r / DP; int n = r % DP;
        float g = 0.f, wvv = 0.f;
        if (n < D) {
            const float* wk = Wk + h * D * D;
            const float* wq = Wq + h * D * D;
            float s = 0.f;
            #pragma unroll
            for (int e = 0; e < D; e++) s += wk[e * D + n] * wq[e * D + m];
            g   = s * scale;
            wvv = hw[h] * Wv[h * D * D + n * D + m];
        }
        s_Gt[i] = g; s_Wvt[i] = wvv;
    }
    for (int i = tid; i < HEADS * DP; i += NTHR) {
        int h = i / DP, n = i % DP;
        float gb = 0.f, bvv = 0.f;
        if (n < D) {
            const float* wk = Wk + h * D * D;
            float s = 0.f;
            #pragma unroll
            for (int e = 0; e < D; e++) s += bq[h * D + e] * wk[e * D + n];
            gb  = s * scale;
            bvv = hw[h] * bv[h * D + n];
        }
        s_gbp[i] = gb; s_bvp[i] = bvv;
    }

    const float* inb = in + (size_t)b * CH * IMGPIX;
    for (int i = tid; i < CH * TILEH * TILEW; i += NTHR) {
        int c   = i / (TILEH * TILEW);
        int rem = i % (TILEH * TILEW);
        int tr  = rem / TILEW;
        int tc  = rem % TILEW;
        int rr = (wi0 - 1) * P + tr; if (rr < 0) rr = -rr; else if (rr >= IMGH) rr = 2 * IMGH - 2 - rr;
        int cc = (wj0 - 1) * P + tc; if (cc < 0) cc = -cc; else if (cc >= IMGW) cc = 2 * IMGW - 2 - cc;
        s_tile[sm_idx<P, TILEH>(c, tr, tc)] = inb[c * IMGPIX + rr * IMGW + cc];
    }
    __syncthreads();

    const int w   = tid % NW;
    const int h   = tid / NW;
    const int lwj = w % TW;
    const int lwi = w / TW;

    // ---- center token ----
    float tok4[D];
    if constexpr (P == 2) {
        #pragma unroll
        for (int c = 0; c < CH; c++)
            #pragma unroll
            for (int pi = 0; pi < 2; pi++) {
                float2 v = ((const float2*)s_tile)[sm_idx2<TILEH>(c, (lwi + 1) * 2 + pi, lwj + 1)];
                tok4[c * 4 + pi * 2] = v.x; tok4[c * 4 + pi * 2 + 1] = v.y;
            }
    } else {
        #pragma unroll
        for (int c = 0; c < CH; c++)
            #pragma unroll
            for (int pi = 0; pi < P; pi++)
                #pragma unroll
                for (int pj = 0; pj < P; pj++)
                    tok4[c * PP + pi * P + pj] =
                        s_tile[sm_idx<P, TILEH>(c, (lwi + 1) * P + pi, (lwj + 1) * P + pj)];
    }

    // ---- u = G_h^T tok4 + gb_h ----
    float u[DP];
    #pragma unroll
    for (int e4 = 0; e4 < DP; e4 += 4) {
        float4 v = *(const float4*)&s_gbp[h * DP + e4];
        u[e4] = v.x; u[e4+1] = v.y; u[e4+2] = v.z; u[e4+3] = v.w;
    }
    #pragma unroll
    for (int m = 0; m < D; m++) {
        float t = tok4[m];
        #pragma unroll
        for (int e4 = 0; e4 < DP; e4 += 4) {
            float4 g = *(const float4*)&s_Gt[(h * D + m) * DP + e4];
            u[e4]   += g.x * t; u[e4+1] += g.y * t;
            u[e4+2] += g.z * t; u[e4+3] += g.w * t;
        }
    }

    // ---- scores ----
    float sc[9];
    float smax = neg_inf();
    #pragma unroll
    for (int di = 0; di < 3; di++)
    #pragma unroll
    for (int dj = 0; dj < 3; dj++) {
        float s = 0.f;
        if constexpr (P == 2) {
            #pragma unroll
            for (int c = 0; c < CH; c++)
                #pragma unroll
                for (int pi = 0; pi < 2; pi++) {
                    float2 v = ((const float2*)s_tile)[sm_idx2<TILEH>(c, (lwi + di) * 2 + pi, lwj + dj)];
                    int e = c * 4 + pi * 2;
                    s += u[e] * v.x + u[e+1] * v.y;
                }
        } else {
            #pragma unroll
            for (int c = 0; c < CH; c++)
                #pragma unroll
                for (int pi = 0; pi < P; pi++)
                    #pragma unroll
                    for (int pj = 0; pj < P; pj++)
                        s += u[c * PP + pi * P + pj] *
                             s_tile[sm_idx<P, TILEH>(c, (lwi + di) * P + pi, (lwj + dj) * P + pj)];
        }
        sc[di * 3 + dj] = s;
        smax = fmaxf(smax, s);
    }

    float den = 0.f;
    #pragma unroll
    for (int t = 0; t < 9; t++) { float e = __expf(sc[t] - smax); sc[t] = e; den += e; }
    float inv = 1.f / den;
    #pragma unroll
    for (int t = 0; t < 9; t++) sc[t] *= inv;

    // ---- weighted token sum ----
    float acc[D];
    #pragma unroll
    for (int d = 0; d < D; d++) acc[d] = 0.f;
    #pragma unroll
    for (int di = 0; di < 3; di++)
    #pragma unroll
    for (int dj = 0; dj < 3; dj++) {
        const float a = sc[di * 3 + dj];
        if constexpr (P == 2) {
            #pragma unroll
            for (int c = 0; c < CH; c++)
                #pragma unroll
                for (int pi = 0; pi < 2; pi++) {
                    float2 v = ((const float2*)s_tile)[sm_idx2<TILEH>(c, (lwi + di) * 2 + pi, lwj + dj)];
                    int e = c * 4 + pi * 2;
                    acc[e] += a * v.x; acc[e+1] += a * v.y;
                }
        } else {
            #pragma unroll
            for (int c = 0; c < CH; c++)
                #pragma unroll
                for (int pi = 0; pi < P; pi++)
                    #pragma unroll
                    for (int pj = 0; pj < P; pj++)
                        acc[c * PP + pi * P + pj] +=
                            a * s_tile[sm_idx<P, TILEH>(c, (lwi + di) * P + pi, (lwj + dj) * P + pj)];
        }
    }

    // ---- projection (hw folded) ----
    float part[DP];
    #pragma unroll
    for (int e4 = 0; e4 < DP; e4 += 4) {
        float4 v = *(const float4*)&s_bvp[h * DP + e4];
        part[e4] = v.x; part[e4+1] = v.y; part[e4+2] = v.z; part[e4+3] = v.w;
    }
    #pragma unroll
    for (int m = 0; m < D; m++) {
        float a = acc[m];
        #pragma unroll
        for (int e4 = 0; e4 < DP; e4 += 4) {
            float4 wv = *(const float4*)&s_Wvt[(h * D + m) * DP + e4];
            part[e4]   += wv.x * a; part[e4+1] += wv.y * a;
            part[e4+2] += wv.z * a; part[e4+3] += wv.w * a;
        }
    }

    // ---- combine heads ----
    if (h > 0) {
        #pragma unroll
        for (int e = 0; e < D; e++)
            s_part[(h - 1) * NW * DR + w * DR + e] = part[e];
    }
    __syncthreads();
    if (h == 0) {
        #pragma unroll
        for (int s = 0; s < HEADS - 1; s++)
            #pragma unroll
            for (int e = 0; e < D; e++)
                part[e] += s_part[s * NW * DR + w * DR + e];

        float* outb = out + (size_t)b * CH * IMGPIX;
        const int wi = wi0 + lwi, wj = wj0 + lwj;
        if constexpr (P == 2) {
            #pragma unroll
            for (int c = 0; c < CH; c++)
                #pragma unroll
                for (int pi = 0; pi < 2; pi++)
                    *(float2*)&outb[c * IMGPIX + (wi * 2 + pi) * IMGW + wj * 2] =
                        make_float2(part[c * 4 + pi * 2], part[c * 4 + pi * 2 + 1]);
        } else {
            #pragma unroll
            for (int c = 0; c < CH; c++)
                #pragma unroll
                for (int pi = 0; pi < P; pi++)
                    #pragma unroll
                    for (int pj = 0; pj < P; pj++)
                        outb[c * IMGPIX + (wi * P + pi) * IMGW + (wj * P + pj)] =
                            part[c * PP + pi * P + pj];
        }
    }
}

// ============================================================================
// fused conv0 (5x5, zero pad 2, cat[x9,x6,x3]) + dehaze epilogue.
// 4 pixels per thread along x; register sliding window amortizes weight LDS.
// ============================================================================
#define FB_X 8    // threads in x (each does 4 px)
#define FB_Y 16
#define FOUT_X 32
#define FOUT_Y 16

__global__ void __launch_bounds__(FB_X*FB_Y)
final_kernel(const float* __restrict__ x,
             const float* __restrict__ conv_w, const float* __restrict__ conv_b,
             float* __restrict__ out)
{
    constexpr int TEH = FOUT_Y + 4, TEW = FOUT_X + 4;   // 20 x 36
    constexpr int NTHR = FB_X * FB_Y;                   // 128
    __shared__ __align__(16) float s_t[9][TEH][TEW];
    __shared__ float s_w[3 * 9 * 25];
    __shared__ float s_b[3];
    __shared__ float s_red[NTHR / 32];

    const int tid = threadIdx.y * FB_X + threadIdx.x;
    for (int i = tid; i < 675; i += NTHR) s_w[i] = conv_w[i];
    if (tid < 3) s_b[tid] = conv_b[tid];

    const int b  = blockIdx.z;
    const int y0 = blockIdx.y * FOUT_Y;
    const int x0 = blockIdx.x * FOUT_X;

    // xg = image max (reduced from p=1 per-block maxes)
    float m = neg_inf();
    for (int i = tid; i < NB1; i += NTHR) m = fmaxf(m, g_bmax[b * NB1 + i]);
    #pragma unroll
    for (int o = 16; o; o >>= 1) m = fmaxf(m, __shfl_xor_sync(0xffffffffu, m, o));
    if ((tid & 31) == 0) s_red[tid >> 5] = m;

    for (int i = tid; i < 9 * TEH * TEW; i += NTHR) {
        int ci  = i / (TEH * TEW);
        int rem = i % (TEH * TEW);
        int ty  = rem / TEW;
        int tx  = rem % TEW;
        int gy = y0 + ty - 2, gx = x0 + tx - 2;
        float v = 0.f;
        if (gy >= 0 && gy < IMGH && gx >= 0 && gx < IMGW) {
            const float* src = (ci < 3) ? g_x9 : (ci < 6) ? g_x6 : g_x3;
            v = src[(((size_t)b * CH + (ci % 3)) * IMGH + gy) * IMGW + gx];
        }
        s_t[ci][ty][tx] = v;
    }
    __syncthreads();

    float xg = s_red[0];
    #pragma unroll
    for (int w = 1; w < NTHR / 32; w++) xg = fmaxf(xg, s_red[w]);

    const int ty  = threadIdx.y;
    const int tx4 = threadIdx.x * 4;

    float acc[3][4];
    #pragma unroll
    for (int co = 0; co < 3; co++)
        #pragma unroll
        for (int px = 0; px < 4; px++) acc[co][px] = s_b[co];

    #pragma unroll
    for (int ci = 0; ci < 9; ci++)
        #pragma unroll
        for (int kh = 0; kh < 5; kh++) {
            const float* rowp = &s_t[ci][ty + kh][tx4];
            float4 a = *(const float4*)(rowp);
            float4 c = *(const float4*)(rowp + 4);
            float rb[8] = {a.x, a.y, a.z, a.w, c.x, c.y, c.z, c.w};
            const float* wrow = &s_w[ci * 25 + kh * 5];
            #pragma unroll
            for (int kw = 0; kw < 5; kw++) {
                float w0 = wrow[kw];
                float w1 = wrow[225 + kw];
                float w2 = wrow[450 + kw];
                #pragma unroll
                for (int px = 0; px < 4; px++) {
                    float v = rb[px + kw];
                    acc[0][px] += w0 * v;
                    acc[1][px] += w1 * v;
                    acc[2][px] += w2 * v;
                }
            }
        }

    const int gy = y0 + ty, gx = x0 + tx4;
    #pragma unroll
    for (int co = 0; co < 3; co++) {
        size_t idx = (((size_t)b * CH + co) * IMGH + gy) * IMGW + gx;
        float4 xv = *(const float4*)&x[idx];
        float4 r;
        float x0v;
        x0v = fmaxf(acc[co][0], 0.f); r.x = fmaxf(xv.x * x0v + (xg - x0v), 0.f);
        x0v = fmaxf(acc[co][1], 0.f); r.y = fmaxf(xv.y * x0v + (xg - x0v), 0.f);
        x0v = fmaxf(acc[co][2], 0.f); r.z = fmaxf(xv.z * x0v + (xg - x0v), 0.f);
        x0v = fmaxf(acc[co][3], 0.f); r.w = fmaxf(xv.w * x0v + (xg - x0v), 0.f);
        *(float4*)&out[idx] = r;
    }
}

// ---------------- launch ----------------------------------------------------
extern "C" void kernel_launch(void* const* d_in, const int* in_sizes, int n_in,
                              void* d_out, int out_size)
{
    (void)in_sizes; (void)n_in; (void)out_size;

    const float* x    = (const float*)d_in[0];
    const float* w3q  = (const float*)d_in[1];
    const float* b3q  = (const float*)d_in[2];
    const float* w3k  = (const float*)d_in[3];
    const float* w3v  = (const float*)d_in[5];
    const float* b3v  = (const float*)d_in[6];
    const float* hw3  = (const float*)d_in[7];
    const float* w6q  = (const float*)d_in[8];
    const float* b6q  = (const float*)d_in[9];
    const float* w6k  = (const float*)d_in[10];
    const float* w6v  = (const float*)d_in[12];
    const float* b6v  = (const float*)d_in[13];
    const float* hw6  = (const float*)d_in[14];
    const float* w9q  = (const float*)d_in[15];
    const float* b9q  = (const float*)d_in[16];
    const float* w9k  = (const float*)d_in[17];
    const float* w9v  = (const float*)d_in[19];
    const float* b9v  = (const float*)d_in[20];
    const float* hw9  = (const float*)d_in[21];
    const float* cw   = (const float*)d_in[22];
    const float* cb   = (const float*)d_in[23];

    float *x3, *x6, *x9;
    cudaGetSymbolAddress((void**)&x3, g_x3);
    cudaGetSymbolAddress((void**)&x6, g_x6);
    cudaGetSymbolAddress((void**)&x9, g_x9);

    // stage p=1: 384x384 windows, 16x16 windows/block, 6 heads fused (+ image max)
    attn1_kernel<16, 16><<<dim3(24, 24, BATCH), 256>>>(x,  x3, w3q, b3q, w3k, w3v, b3v, hw3);
    // stage p=2: 192x192 windows, 8x8 windows/block x 4 head-groups = 256 thr
    attn_split<2, 12, 4, 8, 8><<<dim3(24, 24, BATCH), 256>>>(x3, x6, w6q, b6q, w6k, w6v, b6v, hw6);
    // stage p=3: 128x128 windows, 8x8 windows/block x 2 head-groups = 128 thr
    attn_split<3, 27, 2, 8, 8><<<dim3(16, 16, BATCH), 128>>>(x6, x9, w9q, b9q, w9k, w9v, b9v, hw9);

    final_kernel<<<dim3(IMGW / FOUT_X, IMGH / FOUT_Y, BATCH), dim3(FB_X, FB_Y)>>>(x, cw, cb, (float*)d_out);
}